// round 3
// baseline (speedup 1.0000x reference)
#include <cuda_runtime.h>
#include <math.h>

// Problem constants
#define B_    4
#define C_    64
#define H_    128
#define W_    128
#define HW_   (H_*W_)
#define OFFC_ 32
#define K2_   9
#define OCOFF 27

// ---------------- scratch ----------------
// Per (b,k,y,x): packed clamped corners (y0c<<24 | y1c<<16 | x0c<<8 | x1c)
// and bilinear weights premultiplied by validity and mask.
__device__ int    g_idx[B_ * K2_ * HW_];
__device__ float4 g_wts[B_ * K2_ * HW_];
// weight transposed to [k][c][o]
__device__ float  g_wt[K2_ * C_ * C_];

// ---------------- Stage 0: transpose weight [o][c][k] -> [k][c][o] ----------------
__global__ void transpose_w_kernel(const float* __restrict__ w) {
    int i = blockIdx.x * 256 + threadIdx.x;
    if (i < C_ * C_ * K2_) {
        int o = i / (C_ * K2_);
        int r = i % (C_ * K2_);
        int c = r / K2_;
        int k = r % K2_;
        g_wt[(k * C_ + c) * C_ + o] = w[i];
    }
}

// ---------------- Stage 1: offset conv + bilinear descriptor precompute ----------------
__global__ __launch_bounds__(128) void offset_kernel(
    const float* __restrict__ offset_feat,   // [B,32,H,W]
    const float* __restrict__ w_off,         // [27,32,3,3]
    const float* __restrict__ b_off)         // [27]
{
    __shared__ float s_w[288 * 28];
    __shared__ float s_boff[28];

    const int tid = threadIdx.x;
    const int y   = blockIdx.x & (H_ - 1);
    const int b   = blockIdx.x >> 7;
    const int x   = tid;

    for (int i = tid; i < OCOFF * 288; i += 128) {
        int oc = i / 288;
        int r  = i % 288;             // c*9 + tap
        s_w[r * 28 + oc] = w_off[i];
    }
    if (tid < 28) s_boff[tid] = (tid < OCOFF) ? b_off[tid] : 0.f;
    __syncthreads();

    float acc[28];
#pragma unroll
    for (int j = 0; j < 28; j++) acc[j] = s_boff[j];

    const float* fbase = offset_feat + (size_t)b * OFFC_ * HW_;

#pragma unroll
    for (int ky = 0; ky < 3; ky++) {
        const int iy = y - 1 + ky;
        const bool vy = ((unsigned)iy < (unsigned)H_);
#pragma unroll
        for (int kx = 0; kx < 3; kx++) {
            const int ix = x - 1 + kx;
            const bool v = vy && ((unsigned)ix < (unsigned)W_);
            const int tap = ky * 3 + kx;
            const float* ip = fbase + iy * W_ + ix;
#pragma unroll 4
            for (int c = 0; c < OFFC_; c++) {
                float vv = v ? __ldg(ip + c * HW_) : 0.f;
                const float4* wp = (const float4*)(s_w + (c * 9 + tap) * 28);
#pragma unroll
                for (int j = 0; j < 7; j++) {
                    float4 w4 = wp[j];
                    acc[j * 4 + 0] += vv * w4.x;
                    acc[j * 4 + 1] += vv * w4.y;
                    acc[j * 4 + 2] += vv * w4.z;
                    acc[j * 4 + 3] += vv * w4.w;
                }
            }
        }
    }

#pragma unroll
    for (int k = 0; k < K2_; k++) {
        float dy = acc[2 * k];
        float dx = acc[2 * k + 1];
        float m  = 1.f / (1.f + __expf(-acc[18 + k]));

        float py = (float)(y - 1 + (k / 3)) + dy;
        float px = (float)(x - 1 + (k % 3)) + dx;
        float y0f = floorf(py), x0f = floorf(px);
        float wy1 = py - y0f,   wx1 = px - x0f;
        float wy0 = 1.f - wy1,  wx0 = 1.f - wx1;
        int y0 = (int)y0f, x0 = (int)x0f;
        int y1 = y0 + 1,   x1 = x0 + 1;

        bool vy0 = ((unsigned)y0 < (unsigned)H_);
        bool vy1 = ((unsigned)y1 < (unsigned)H_);
        bool vx0 = ((unsigned)x0 < (unsigned)W_);
        bool vx1 = ((unsigned)x1 < (unsigned)W_);

        float w00 = wy0 * wx0 * m * (float)(vy0 && vx0);
        float w01 = wy0 * wx1 * m * (float)(vy0 && vx1);
        float w10 = wy1 * wx0 * m * (float)(vy1 && vx0);
        float w11 = wy1 * wx1 * m * (float)(vy1 && vx1);

        int y0c = min(max(y0, 0), H_ - 1);
        int y1c = min(max(y1, 0), H_ - 1);
        int x0c = min(max(x0, 0), W_ - 1);
        int x1c = min(max(x1, 0), W_ - 1);

        int base = ((b * K2_ + k) * H_ + y) * W_ + x;
        g_idx[base] = (y0c << 24) | (y1c << 16) | (x0c << 8) | x1c;
        g_wts[base] = make_float4(w00, w01, w10, w11);
    }
}

// ---------------- Stage 2: fused sampling (smem-cached) + GEMM ----------------
// block = one (b,y) output row. Channel chunks of 8; per chunk cache x rows
// [y-4, y+4] in smem; per tap gather from smem (rare global fallback) and
// run K=8 register-tiled GEMM (4o x 8p per thread).
#define NC_   8          // channels per chunk
#define NR_   9          // cached rows (y-4..y+4)

// dynamic smem layout (bytes)
#define SM_DW  0                         // float4[9*128]  = 18432
#define SM_DI  18432                     // int[9*128]     = 4608
#define SM_X   23040                     // float[8*9*128] = 36864
#define SM_S   59904                     // float[8*128]   = 4096
#define SM_W   64000                     // float[8*64]    = 2048
#define SM_TOT 66048

__global__ __launch_bounds__(256) void deform_kernel(
    const float* __restrict__ x,     // [B,64,H,W]
    const float* __restrict__ bias,  // [64]
    float* __restrict__ out)         // [B,64,H,W]
{
    extern __shared__ char smem[];
    float4* sDw = (float4*)(smem + SM_DW);
    int*    sDi = (int*)   (smem + SM_DI);
    float*  sX  = (float*) (smem + SM_X);
    float*  sS  = (float*) (smem + SM_S);
    float*  sW  = (float*) (smem + SM_W);

    const int tid = threadIdx.x;
    const int y   = blockIdx.x & (H_ - 1);
    const int b   = blockIdx.x >> 7;
    const int ylo = y - 4;

    // fill mapping: pixel + channel-group
    const int px = tid & 127;
    const int gg = tid >> 7;          // 0/1 -> channels gg*4 .. gg*4+3

    // gemm mapping
    const int tx = tid & 15;
    const int ty = tid >> 4;
    const int p0 = tx * 8;
    const int o0 = ty * 4;

    // ---- stage: load descriptors for this (b,y) row ----
    for (int i = tid; i < K2_ * W_; i += 256) {
        int k  = i >> 7;
        int xx = i & 127;
        int src = ((b * K2_ + k) * H_ + y) * W_ + xx;
        sDw[i] = g_wts[src];
        sDi[i] = g_idx[src];
    }

    float acc[4][8];
#pragma unroll
    for (int i = 0; i < 4; i++)
#pragma unroll
        for (int j = 0; j < 8; j++) acc[i][j] = 0.f;

    const float* xb = x + (size_t)b * C_ * HW_;

#pragma unroll 1
    for (int cc = 0; cc < C_ / NC_; cc++) {
        __syncthreads();   // previous GEMM / fill readers done

        // ---- cache x rows [ylo, ylo+8] for this 8-channel chunk ----
        // 8*9*128 floats = 2304 float4, 9 per thread
#pragma unroll
        for (int it = 0; it < 9; it++) {
            int i   = tid + it * 256;           // float4 index
            int ch  = i / 288;                  // 288 float4 per channel
            int rem = i - ch * 288;
            int rs  = rem >> 5;                 // row slot 0..8
            int x4  = rem & 31;
            int row = ylo + rs;
            if ((unsigned)row < (unsigned)H_) {
                const float4* src = (const float4*)(xb + (size_t)(cc * NC_ + ch) * HW_ + row * W_) + x4;
                *(float4*)(sX + (ch * NR_ + rs) * W_ + x4 * 4) = *src;
            }
        }
        __syncthreads();   // sX visible

#pragma unroll 1
        for (int k = 0; k < K2_; k++) {
            if (k) __syncthreads();   // previous GEMM readers of sW/sS done

            // ---- load W chunk [8c][64o] ----
            const float* wk = g_wt + (k * C_ + cc * NC_) * C_;
            sW[tid]       = wk[tid];
            sW[tid + 256] = wk[tid + 256];

            // ---- bilinear fill of sS[8c][128p] from sX ----
            {
                float4 wv = sDw[k * W_ + px];
                int    di = sDi[k * W_ + px];
                int y0c = (di >> 24) & 255;
                int y1c = (di >> 16) & 255;
                int x0c = (di >> 8)  & 255;
                int x1c = di & 255;
                int s0  = y0c - ylo;
                int s1  = y1c - ylo;
                bool in0 = ((unsigned)s0 < (unsigned)NR_);
                bool in1 = ((unsigned)s1 < (unsigned)NR_);
#pragma unroll
                for (int j = 0; j < 4; j++) {
                    int ch = gg * 4 + j;
                    const float* gp = xb + (size_t)(cc * NC_ + ch) * HW_;
                    const float* sp = sX + ch * NR_ * W_;
                    float v00 = in0 ? sp[s0 * W_ + x0c] : __ldg(gp + y0c * W_ + x0c);
                    float v01 = in0 ? sp[s0 * W_ + x1c] : __ldg(gp + y0c * W_ + x1c);
                    float v10 = in1 ? sp[s1 * W_ + x0c] : __ldg(gp + y1c * W_ + x0c);
                    float v11 = in1 ? sp[s1 * W_ + x1c] : __ldg(gp + y1c * W_ + x1c);
                    sS[ch * W_ + px] = wv.x * v00 + wv.y * v01 + wv.z * v10 + wv.w * v11;
                }
            }
            __syncthreads();

            // ---- GEMM: acc += W[c][o0..3] * S[c][p0..7], K=8 ----
#pragma unroll
            for (int c = 0; c < NC_; c++) {
                float4 w4 = *(const float4*)&sW[c * C_ + o0];
                float4 s0 = *(const float4*)&sS[c * W_ + p0];
                float4 s1 = *(const float4*)&sS[c * W_ + p0 + 4];
                acc[0][0] += w4.x * s0.x; acc[0][1] += w4.x * s0.y;
                acc[0][2] += w4.x * s0.z; acc[0][3] += w4.x * s0.w;
                acc[0][4] += w4.x * s1.x; acc[0][5] += w4.x * s1.y;
                acc[0][6] += w4.x * s1.z; acc[0][7] += w4.x * s1.w;
                acc[1][0] += w4.y * s0.x; acc[1][1] += w4.y * s0.y;
                acc[1][2] += w4.y * s0.z; acc[1][3] += w4.y * s0.w;
                acc[1][4] += w4.y * s1.x; acc[1][5] += w4.y * s1.y;
                acc[1][6] += w4.y * s1.z; acc[1][7] += w4.y * s1.w;
                acc[2][0] += w4.z * s0.x; acc[2][1] += w4.z * s0.y;
                acc[2][2] += w4.z * s0.z; acc[2][3] += w4.z * s0.w;
                acc[2][4] += w4.z * s1.x; acc[2][5] += w4.z * s1.y;
                acc[2][6] += w4.z * s1.z; acc[2][7] += w4.z * s1.w;
                acc[3][0] += w4.w * s0.x; acc[3][1] += w4.w * s0.y;
                acc[3][2] += w4.w * s0.z; acc[3][3] += w4.w * s0.w;
                acc[3][4] += w4.w * s1.x; acc[3][5] += w4.w * s1.y;
                acc[3][6] += w4.w * s1.z; acc[3][7] += w4.w * s1.w;
            }
        }
    }

    // epilogue
#pragma unroll
    for (int i = 0; i < 4; i++) {
        float bv = __ldg(&bias[o0 + i]);
        float* op = out + (((size_t)b * C_ + (o0 + i)) * H_ + y) * W_ + p0;
        float4 r0 = make_float4(acc[i][0] + bv, acc[i][1] + bv,
                                acc[i][2] + bv, acc[i][3] + bv);
        float4 r1 = make_float4(acc[i][4] + bv, acc[i][5] + bv,
                                acc[i][6] + bv, acc[i][7] + bv);
        *(float4*)op       = r0;
        *(float4*)(op + 4) = r1;
    }
}

// ---------------- launch ----------------
extern "C" void kernel_launch(void* const* d_in, const int* in_sizes, int n_in,
                              void* d_out, int out_size) {
    const float* x           = (const float*)d_in[0];
    const float* offset_feat = (const float*)d_in[1];
    const float* w_off       = (const float*)d_in[2];
    const float* b_off       = (const float*)d_in[3];
    const float* weight      = (const float*)d_in[4];
    const float* bias        = (const float*)d_in[5];
    float* out = (float*)d_out;

    static bool attr_set = false;
    if (!attr_set) {
        cudaFuncSetAttribute(deform_kernel,
                             cudaFuncAttributeMaxDynamicSharedMemorySize, SM_TOT);
        attr_set = true;
    }

    transpose_w_kernel<<<(C_ * C_ * K2_ + 255) / 256, 256>>>(weight);
    offset_kernel<<<B_ * H_, 128>>>(offset_feat, w_off, b_off);
    deform_kernel<<<B_ * H_, 256, SM_TOT>>>(x, bias, out);
}

// round 5
// speedup vs baseline: 1.2606x; 1.2606x over previous
#include <cuda_runtime.h>
#include <math.h>
#include <cstdint>

// Problem constants
#define B_    4
#define C_    64
#define H_    128
#define W_    128
#define HW_   (H_*W_)
#define OFFC_ 32
#define K2_   9
#define OCOFF 27
#define PAD_  65

// ---------------- scratch ----------------
__device__ int    g_idx[B_ * K2_ * HW_];   // packed clamped corners
__device__ float4 g_wts[B_ * K2_ * HW_];   // premultiplied bilinear weights
__device__ float  g_wt[K2_ * C_ * C_];     // weight transposed to [k][c][o]
__device__ float  g_xt[B_ * HW_ * C_];     // x in NHWC: [b][y][x][c]

// ---------------- f32x2 helpers (base sm_100 ISA, no 'a' features) ----------------
__device__ __forceinline__ void ffma2(unsigned long long& d,
                                      unsigned long long a,
                                      unsigned long long b) {
    asm("fma.rn.f32x2 %0, %1, %2, %0;" : "+l"(d) : "l"(a), "l"(b));
}
__device__ __forceinline__ unsigned long long dup2(float s) {
    unsigned long long d;
    asm("mov.b64 %0, {%1, %1};" : "=l"(d) : "f"(s));
    return d;
}
__device__ __forceinline__ void unpack2(unsigned long long v, float& lo, float& hi) {
    asm("mov.b64 {%0, %1}, %2;" : "=f"(lo), "=f"(hi) : "l"(v));
}

// ---------------- Stage 0a: transpose weight [o][c][k] -> [k][c][o] ----------------
__global__ void transpose_w_kernel(const float* __restrict__ w) {
    int i = blockIdx.x * 256 + threadIdx.x;
    if (i < C_ * C_ * K2_) {
        int o = i / (C_ * K2_);
        int r = i % (C_ * K2_);
        int c = r / K2_;
        int k = r % K2_;
        g_wt[(k * C_ + c) * C_ + o] = w[i];
    }
}

// ---------------- Stage 0b: x NCHW -> NHWC ----------------
// block = one (b,y) row. Read 64 channels x 128 px coalesced, transpose in
// smem, write 32KB contiguous.
__global__ __launch_bounds__(256) void nhwc_kernel(const float* __restrict__ x) {
    __shared__ float st[C_ * 129];
    const int tid = threadIdx.x;
    const int y   = blockIdx.x & (H_ - 1);
    const int b   = blockIdx.x >> 7;

    const float* src = x + ((size_t)b * C_ * H_ + y) * W_;
#pragma unroll
    for (int i = 0; i < 8; i++) {
        int idx = tid + i * 256;          // over 2048 float4
        int c   = idx >> 5;
        int x4  = idx & 31;
        float4 v = __ldg((const float4*)(src + (size_t)c * HW_) + x4);
        float* d = st + c * 129 + x4 * 4;
        d[0] = v.x; d[1] = v.y; d[2] = v.z; d[3] = v.w;
    }
    __syncthreads();

    float* dst = g_xt + ((size_t)(b * H_ + y) * W_) * C_;
#pragma unroll
    for (int i = 0; i < 8; i++) {
        int idx = tid + i * 256;          // over 2048 float4
        int px  = idx >> 4;
        int cq  = idx & 15;
        float4 v;
        v.x = st[(cq * 4 + 0) * 129 + px];
        v.y = st[(cq * 4 + 1) * 129 + px];
        v.z = st[(cq * 4 + 2) * 129 + px];
        v.w = st[(cq * 4 + 3) * 129 + px];
        *((float4*)(dst + (size_t)px * C_) + cq) = v;
    }
}

// ---------------- Stage 1: offset conv + bilinear descriptor precompute ----------------
__global__ __launch_bounds__(128) void offset_kernel(
    const float* __restrict__ offset_feat,   // [B,32,H,W]
    const float* __restrict__ w_off,         // [27,32,3,3]
    const float* __restrict__ b_off)         // [27]
{
    __shared__ float s_w[288 * 28];
    __shared__ float s_boff[28];

    const int tid = threadIdx.x;
    const int y   = blockIdx.x & (H_ - 1);
    const int b   = blockIdx.x >> 7;
    const int x   = tid;

    for (int i = tid; i < OCOFF * 288; i += 128) {
        int oc = i / 288;
        int r  = i % 288;
        s_w[r * 28 + oc] = w_off[i];
    }
    if (tid < 28) s_boff[tid] = (tid < OCOFF) ? b_off[tid] : 0.f;
    __syncthreads();

    float acc[28];
#pragma unroll
    for (int j = 0; j < 28; j++) acc[j] = s_boff[j];

    const float* fbase = offset_feat + (size_t)b * OFFC_ * HW_;

#pragma unroll
    for (int ky = 0; ky < 3; ky++) {
        const int iy = y - 1 + ky;
        const bool vy = ((unsigned)iy < (unsigned)H_);
#pragma unroll
        for (int kx = 0; kx < 3; kx++) {
            const int ix = x - 1 + kx;
            const bool v = vy && ((unsigned)ix < (unsigned)W_);
            const int tap = ky * 3 + kx;
            const float* ip = fbase + iy * W_ + ix;
#pragma unroll 4
            for (int c = 0; c < OFFC_; c++) {
                float vv = v ? __ldg(ip + c * HW_) : 0.f;
                const float4* wp = (const float4*)(s_w + (c * 9 + tap) * 28);
#pragma unroll
                for (int j = 0; j < 7; j++) {
                    float4 w4 = wp[j];
                    acc[j * 4 + 0] += vv * w4.x;
                    acc[j * 4 + 1] += vv * w4.y;
                    acc[j * 4 + 2] += vv * w4.z;
                    acc[j * 4 + 3] += vv * w4.w;
                }
            }
        }
    }

#pragma unroll
    for (int k = 0; k < K2_; k++) {
        float dy = acc[2 * k];
        float dx = acc[2 * k + 1];
        float m  = 1.f / (1.f + __expf(-acc[18 + k]));

        float py = (float)(y - 1 + (k / 3)) + dy;
        float px = (float)(x - 1 + (k % 3)) + dx;
        float y0f = floorf(py), x0f = floorf(px);
        float wy1 = py - y0f,   wx1 = px - x0f;
        float wy0 = 1.f - wy1,  wx0 = 1.f - wx1;
        int y0 = (int)y0f, x0 = (int)x0f;
        int y1 = y0 + 1,   x1 = x0 + 1;

        bool vy0 = ((unsigned)y0 < (unsigned)H_);
        bool vy1 = ((unsigned)y1 < (unsigned)H_);
        bool vx0 = ((unsigned)x0 < (unsigned)W_);
        bool vx1 = ((unsigned)x1 < (unsigned)W_);

        float w00 = wy0 * wx0 * m * (float)(vy0 && vx0);
        float w01 = wy0 * wx1 * m * (float)(vy0 && vx1);
        float w10 = wy1 * wx0 * m * (float)(vy1 && vx0);
        float w11 = wy1 * wx1 * m * (float)(vy1 && vx1);

        int y0c = min(max(y0, 0), H_ - 1);
        int y1c = min(max(y1, 0), H_ - 1);
        int x0c = min(max(x0, 0), W_ - 1);
        int x1c = min(max(x1, 0), W_ - 1);

        int base = ((b * K2_ + k) * H_ + y) * W_ + x;
        g_idx[base] = (y0c << 24) | (y1c << 16) | (x0c << 8) | x1c;
        g_wts[base] = make_float4(w00, w01, w10, w11);
    }
}

// ---------------- Stage 2: NHWC gather fill + f32x2-paired GEMM ----------------
// block = one (b,y) row, 256 threads. Per tap: fill S[128px][64c] (pad 65)
// with fully-coalesced NHWC corner loads (lanes -> channels), then GEMM
// D[128px,64o] += S * W_k with packed fma.rn.f32x2 (o-pairs).
// smem: sW 4096 floats + sS 128*65 floats = 49664 B dynamic.
__global__ __launch_bounds__(256) void deform_kernel(
    const float* __restrict__ bias,  // [64]
    float* __restrict__ out)         // [B,64,H,W]
{
    extern __shared__ float dsm[];
    float* sW = dsm;                  // [c][o] 64x64
    float* sS = dsm + 4096;           // [px][PAD_]

    const int tid = threadIdx.x;
    const int wid = tid >> 5;
    const int lid = tid & 31;
    const int y   = blockIdx.x & (H_ - 1);
    const int b   = blockIdx.x >> 7;

    const int o0 = wid * 8;           // 8 o per thread (4 pairs)

    unsigned long long acc[4][4];     // [px_i][o_pair]
#pragma unroll
    for (int i = 0; i < 4; i++)
#pragma unroll
        for (int q = 0; q < 4; q++) acc[i][q] = 0ull;

    const float* xtb = g_xt + (size_t)b * HW_ * C_;

#pragma unroll 1
    for (int k = 0; k < K2_; k++) {
        // ---- load W_k [c][o] ----
        {
            const float4* wsrc = (const float4*)(g_wt + k * C_ * C_);
            float4* wdst = (float4*)sW;
#pragma unroll
            for (int i = 0; i < 4; i++)
                wdst[tid + i * 256] = __ldg(wsrc + tid + i * 256);
        }

        // ---- fill S: 32 tasks/warp, task = (px, chalf), lanes -> channels ----
        const int dbase = ((b * K2_ + k) * H_ + y) * W_;
#pragma unroll 2
        for (int j = 0; j < 32; j++) {
            const int t  = wid * 32 + j;
            const int px = t >> 1;
            const int ch = ((t & 1) << 5) + lid;
            const float4 wv = __ldg(&g_wts[dbase + px]);
            const int    di = __ldg(&g_idx[dbase + px]);
            const int y0c = (di >> 24) & 255, y1c = (di >> 16) & 255;
            const int x0c = (di >> 8) & 255,  x1c = di & 255;
            const float* p00 = xtb + (size_t)(y0c * W_ + x0c) * C_ + ch;
            const float* p01 = xtb + (size_t)(y0c * W_ + x1c) * C_ + ch;
            const float* p10 = xtb + (size_t)(y1c * W_ + x0c) * C_ + ch;
            const float* p11 = xtb + (size_t)(y1c * W_ + x1c) * C_ + ch;
            float v = wv.x * __ldg(p00) + wv.y * __ldg(p01)
                    + wv.z * __ldg(p10) + wv.w * __ldg(p11);
            sS[px * PAD_ + ch] = v;
        }
        __syncthreads();

        // ---- GEMM: acc[i][q] += W[c][o-pairs] * S[lid+32i][c] ----
#pragma unroll 4
        for (int c = 0; c < C_; c++) {
            const ulonglong2 wA = *(const ulonglong2*)(sW + c * C_ + o0);
            const ulonglong2 wB = *(const ulonglong2*)(sW + c * C_ + o0 + 4);
#pragma unroll
            for (int i = 0; i < 4; i++) {
                const unsigned long long sd = dup2(sS[(lid + 32 * i) * PAD_ + c]);
                ffma2(acc[i][0], wA.x, sd);
                ffma2(acc[i][1], wA.y, sd);
                ffma2(acc[i][2], wB.x, sd);
                ffma2(acc[i][3], wB.y, sd);
            }
        }
        __syncthreads();   // guard sW/sS rewrite next tap
    }

    // ---- epilogue ----
    float bv[8];
#pragma unroll
    for (int q = 0; q < 8; q++) bv[q] = __ldg(&bias[o0 + q]);

#pragma unroll
    for (int i = 0; i < 4; i++) {
        const int px = lid + 32 * i;
#pragma unroll
        for (int q = 0; q < 4; q++) {
            float f0, f1;
            unpack2(acc[i][q], f0, f1);
            const int o = o0 + 2 * q;
            out[(((size_t)b * C_ + o)     * H_ + y) * W_ + px] = f0 + bv[2 * q];
            out[(((size_t)b * C_ + o + 1) * H_ + y) * W_ + px] = f1 + bv[2 * q + 1];
        }
    }
}

// ---------------- launch ----------------
extern "C" void kernel_launch(void* const* d_in, const int* in_sizes, int n_in,
                              void* d_out, int out_size) {
    const float* x           = (const float*)d_in[0];
    const float* offset_feat = (const float*)d_in[1];
    const float* w_off       = (const float*)d_in[2];
    const float* b_off       = (const float*)d_in[3];
    const float* weight      = (const float*)d_in[4];
    const float* bias        = (const float*)d_in[5];
    float* out = (float*)d_out;

    static bool attr_set = false;
    if (!attr_set) {
        cudaFuncSetAttribute(deform_kernel,
                             cudaFuncAttributeMaxDynamicSharedMemorySize,
                             (4096 + 128 * PAD_) * 4);
        attr_set = true;
    }

    transpose_w_kernel<<<(C_ * C_ * K2_ + 255) / 256, 256>>>(weight);
    nhwc_kernel<<<B_ * H_, 256>>>(x);
    offset_kernel<<<B_ * H_, 128>>>(offset_feat, w_off, b_off);
    deform_kernel<<<B_ * H_, 256, (4096 + 128 * PAD_) * 4>>>(bias, out);
}

// round 6
// speedup vs baseline: 2.1785x; 1.7281x over previous
#include <cuda_runtime.h>
#include <math.h>
#include <cstdint>

typedef unsigned long long ull;

// Problem constants
#define B_    4
#define C_    64
#define H_    128
#define W_    128
#define HW_   (H_*W_)
#define OFFC_ 32
#define K2_   9
#define OCOFF 27

// ---------------- scratch ----------------
__device__ int    g_idx[B_ * K2_ * HW_];   // packed clamped corners
__device__ float4 g_wts[B_ * K2_ * HW_];   // premultiplied bilinear weights
__device__ float  g_xt[B_ * HW_ * C_];     // x in NHWC: [b][y][x][c]
// W^T as bf16x2 pairs, split hi/lo: [k][s][o][36 stride, 32 pairs used]
__device__ uint32_t g_wb[K2_ * 2 * C_ * 36];

// ---------------- helpers ----------------
__device__ __forceinline__ uint32_t bf16x2_pack(float hi_up, float lo_lo) {
    uint32_t d;
    asm("cvt.rn.bf16x2.f32 %0, %1, %2;" : "=r"(d) : "f"(hi_up), "f"(lo_lo));
    return d;   // upper = hi_up, lower = lo_lo
}
__device__ __forceinline__ void ffma2(ull& d, ull a, ull b) {
    asm("fma.rn.f32x2 %0, %1, %2, %0;" : "+l"(d) : "l"(a), "l"(b));
}
__device__ __forceinline__ ull dup2(float s) {
    ull d;
    asm("mov.b64 %0, {%1, %1};" : "=l"(d) : "f"(s));
    return d;
}
__device__ __forceinline__ void mma_bf16(float4& d,
                                         uint32_t a0, uint32_t a1, uint32_t a2, uint32_t a3,
                                         uint32_t b0, uint32_t b1) {
    asm volatile(
        "mma.sync.aligned.m16n8k16.row.col.f32.bf16.bf16.f32 "
        "{%0,%1,%2,%3}, {%4,%5,%6,%7}, {%8,%9}, {%0,%1,%2,%3};"
        : "+f"(d.x), "+f"(d.y), "+f"(d.z), "+f"(d.w)
        : "r"(a0), "r"(a1), "r"(a2), "r"(a3), "r"(b0), "r"(b1));
}

// ---------------- Stage 0a: weight -> bf16 hi/lo pairs, [k][s][o][pair] ----------------
__global__ void prep_w_kernel(const float* __restrict__ w) {
    int i = blockIdx.x * 256 + threadIdx.x;    // over 64o * 32p * 9k
    if (i >= C_ * 32 * K2_) return;
    int k = i % K2_;
    int t = i / K2_;
    int p = t % 32;
    int o = t / 32;
    float v0 = w[((size_t)o * C_ + 2 * p)     * K2_ + k];
    float v1 = w[((size_t)o * C_ + 2 * p + 1) * K2_ + k];
    uint32_t h = bf16x2_pack(v1, v0);
    float r0 = __uint_as_float(h << 16);
    float r1 = __uint_as_float(h & 0xffff0000u);
    uint32_t l = bf16x2_pack(v1 - r1, v0 - r0);
    g_wb[((size_t)(k * 2 + 0) * C_ + o) * 36 + p] = h;
    g_wb[((size_t)(k * 2 + 1) * C_ + o) * 36 + p] = l;
}

// ---------------- Stage 0b: x NCHW -> NHWC ----------------
__global__ __launch_bounds__(256) void nhwc_kernel(const float* __restrict__ x) {
    __shared__ float st[C_ * 129];
    const int tid = threadIdx.x;
    const int y   = blockIdx.x & (H_ - 1);
    const int b   = blockIdx.x >> 7;

    const float* src = x + ((size_t)b * C_ * H_ + y) * W_;
#pragma unroll
    for (int i = 0; i < 8; i++) {
        int idx = tid + i * 256;
        int c   = idx >> 5;
        int x4  = idx & 31;
        float4 v = __ldg((const float4*)(src + (size_t)c * HW_) + x4);
        float* d = st + c * 129 + x4 * 4;
        d[0] = v.x; d[1] = v.y; d[2] = v.z; d[3] = v.w;
    }
    __syncthreads();

    float* dst = g_xt + ((size_t)(b * H_ + y) * W_) * C_;
#pragma unroll
    for (int i = 0; i < 8; i++) {
        int idx = tid + i * 256;
        int px  = idx >> 4;
        int cq  = idx & 15;
        float4 v;
        v.x = st[(cq * 4 + 0) * 129 + px];
        v.y = st[(cq * 4 + 1) * 129 + px];
        v.z = st[(cq * 4 + 2) * 129 + px];
        v.w = st[(cq * 4 + 3) * 129 + px];
        *((float4*)(dst + (size_t)px * C_) + cq) = v;
    }
}

// ---------------- Stage 1: offset conv + bilinear descriptor precompute ----------------
__global__ __launch_bounds__(128) void offset_kernel(
    const float* __restrict__ offset_feat,   // [B,32,H,W]
    const float* __restrict__ w_off,         // [27,32,3,3]
    const float* __restrict__ b_off)         // [27]
{
    __shared__ __align__(16) float s_w[288 * 28];
    __shared__ __align__(16) float s_boff[28];

    const int tid = threadIdx.x;
    const int y   = blockIdx.x & (H_ - 1);
    const int b   = blockIdx.x >> 7;
    const int x   = tid;

    for (int i = tid; i < OCOFF * 288; i += 128) {
        int oc = i / 288;
        int r  = i % 288;
        s_w[r * 28 + oc] = w_off[i];
    }
    if (tid < 28) s_boff[tid] = (tid < OCOFF) ? b_off[tid] : 0.f;
    __syncthreads();

    ull acc2[14];
#pragma unroll
    for (int j = 0; j < 14; j++) acc2[j] = ((const ull*)s_boff)[j];

    const float* fbase = offset_feat + (size_t)b * OFFC_ * HW_;

#pragma unroll
    for (int ky = 0; ky < 3; ky++) {
        const int iy = y - 1 + ky;
        const bool vy = ((unsigned)iy < (unsigned)H_);
#pragma unroll
        for (int kx = 0; kx < 3; kx++) {
            const int ix = x - 1 + kx;
            const bool v = vy && ((unsigned)ix < (unsigned)W_);
            const int tap = ky * 3 + kx;
            const float* ip = fbase + iy * W_ + ix;
#pragma unroll 4
            for (int c = 0; c < OFFC_; c++) {
                float vv = v ? __ldg(ip + c * HW_) : 0.f;
                ull v2 = dup2(vv);
                const ulonglong2* wp = (const ulonglong2*)(s_w + (c * 9 + tap) * 28);
#pragma unroll
                for (int j = 0; j < 7; j++) {
                    ulonglong2 ww = wp[j];
                    ffma2(acc2[2 * j],     ww.x, v2);
                    ffma2(acc2[2 * j + 1], ww.y, v2);
                }
            }
        }
    }

    float acc[28];
#pragma unroll
    for (int j = 0; j < 14; j++) {
        asm("mov.b64 {%0, %1}, %2;" : "=f"(acc[2 * j]), "=f"(acc[2 * j + 1]) : "l"(acc2[j]));
    }

#pragma unroll
    for (int k = 0; k < K2_; k++) {
        float dy = acc[2 * k];
        float dx = acc[2 * k + 1];
        float m  = 1.f / (1.f + __expf(-acc[18 + k]));

        float py = (float)(y - 1 + (k / 3)) + dy;
        float px = (float)(x - 1 + (k % 3)) + dx;
        float y0f = floorf(py), x0f = floorf(px);
        float wy1 = py - y0f,   wx1 = px - x0f;
        float wy0 = 1.f - wy1,  wx0 = 1.f - wx1;
        int y0 = (int)y0f, x0 = (int)x0f;
        int y1 = y0 + 1,   x1 = x0 + 1;

        bool vy0 = ((unsigned)y0 < (unsigned)H_);
        bool vy1 = ((unsigned)y1 < (unsigned)H_);
        bool vx0 = ((unsigned)x0 < (unsigned)W_);
        bool vx1 = ((unsigned)x1 < (unsigned)W_);

        float w00 = wy0 * wx0 * m * (float)(vy0 && vx0);
        float w01 = wy0 * wx1 * m * (float)(vy0 && vx1);
        float w10 = wy1 * wx0 * m * (float)(vy1 && vx0);
        float w11 = wy1 * wx1 * m * (float)(vy1 && vx1);

        int y0c = min(max(y0, 0), H_ - 1);
        int y1c = min(max(y1, 0), H_ - 1);
        int x0c = min(max(x0, 0), W_ - 1);
        int x1c = min(max(x1, 0), W_ - 1);

        int base = ((b * K2_ + k) * H_ + y) * W_ + x;
        g_idx[base] = (y0c << 24) | (y1c << 16) | (x0c << 8) | x1c;
        g_wts[base] = make_float4(w00, w01, w10, w11);
    }
}

// ---------------- Stage 2: NHWC gather fill + mma.sync bf16 2-split GEMM ----------------
// block = one (b,y) row, 256 threads / 8 warps. Warp w owns px strip [16w,16w+16).
// Per tap: cooperative sB copy, warp-private sA bilinear fill (bf16 hi/lo pairs),
// then D[16px,64o] += A*B^T via 96 mma.sync (hh + hl + lh).
// smem u32: sAh[128][36] sAl[128][36] sBh[64][36] sBl[64][36] = 55296 B
#define SMU_AH 0
#define SMU_AL 4608
#define SMU_BH 9216
#define SMU_BL 11520
#define SMU_TOT 13824

__global__ __launch_bounds__(256) void deform_kernel(
    const float* __restrict__ bias,  // [64]
    float* __restrict__ out)         // [B,64,H,W]
{
    extern __shared__ uint32_t usm[];
    uint32_t* sAh = usm + SMU_AH;
    uint32_t* sAl = usm + SMU_AL;
    uint32_t* sBh = usm + SMU_BH;

    const int tid = threadIdx.x;
    const int wid = tid >> 5;
    const int lid = tid & 31;
    const int y   = blockIdx.x & (H_ - 1);
    const int b   = blockIdx.x >> 7;

    const int pxw = wid * 16;
    const int g   = lid >> 2;
    const int tg  = lid & 3;

    float4 acc[8];
#pragma unroll
    for (int nt = 0; nt < 8; nt++) acc[nt] = make_float4(0.f, 0.f, 0.f, 0.f);

    const float* xtb = g_xt + (size_t)b * HW_ * C_;
    const int fpx = pxw + 2 * 0 + (lid >> 4);   // base parity for fill
    const int c4  = lid & 15;

    // fragment base pointers
    uint32_t* pAh = sAh + (pxw + g) * 36 + tg;
    uint32_t* pAl = sAl + (pxw + g) * 36 + tg;
    uint32_t* pB  = sBh + g * 36 + tg;          // hi at +0, lo at +2304

#pragma unroll 1
    for (int k = 0; k < K2_; k++) {
        if (k) __syncthreads();   // all warps done reading sB of previous tap

        // ---- cooperative copy of B tiles (hi+lo contiguous: 4608 u32) ----
        {
            const float4* src = (const float4*)(g_wb + (size_t)k * 2 * C_ * 36);
            float4* dst = (float4*)(usm + SMU_BH);
#pragma unroll
            for (int i = 0; i < 4; i++)
                dst[tid + i * 256] = __ldg(src + tid + i * 256);
            int i4 = tid + 1024;
            if (i4 < 1152) dst[i4] = __ldg(src + i4);
        }

        // ---- warp-private bilinear fill of sA rows [pxw, pxw+16) ----
        {
            const int dbase = ((b * K2_ + k) * H_ + y) * W_;
#pragma unroll
            for (int j = 0; j < 8; j++) {
                const int px = pxw + 2 * j + (lid >> 4);
                const float4 wv = __ldg(&g_wts[dbase + px]);
                const int    di = __ldg(&g_idx[dbase + px]);
                const int y0c = (di >> 24) & 255, y1c = (di >> 16) & 255;
                const int x0c = (di >> 8) & 255,  x1c = di & 255;
                const float4 q00 = __ldg((const float4*)(xtb + (size_t)(y0c * W_ + x0c) * C_) + c4);
                const float4 q01 = __ldg((const float4*)(xtb + (size_t)(y0c * W_ + x1c) * C_) + c4);
                const float4 q10 = __ldg((const float4*)(xtb + (size_t)(y1c * W_ + x0c) * C_) + c4);
                const float4 q11 = __ldg((const float4*)(xtb + (size_t)(y1c * W_ + x1c) * C_) + c4);
                float v0 = wv.x * q00.x + wv.y * q01.x + wv.z * q10.x + wv.w * q11.x;
                float v1 = wv.x * q00.y + wv.y * q01.y + wv.z * q10.y + wv.w * q11.y;
                float v2 = wv.x * q00.z + wv.y * q01.z + wv.z * q10.z + wv.w * q11.z;
                float v3 = wv.x * q00.w + wv.y * q01.w + wv.z * q10.w + wv.w * q11.w;
                uint32_t h0 = bf16x2_pack(v1, v0);
                uint32_t h1 = bf16x2_pack(v3, v2);
                float r0 = __uint_as_float(h0 << 16);
                float r1 = __uint_as_float(h0 & 0xffff0000u);
                float r2 = __uint_as_float(h1 << 16);
                float r3 = __uint_as_float(h1 & 0xffff0000u);
                uint32_t l0 = bf16x2_pack(v1 - r1, v0 - r0);
                uint32_t l1 = bf16x2_pack(v3 - r3, v2 - r2);
                uint2 hv = make_uint2(h0, h1);
                uint2 lv = make_uint2(l0, l1);
                *(uint2*)&sAh[px * 36 + 2 * c4] = hv;
                *(uint2*)&sAl[px * 36 + 2 * c4] = lv;
            }
        }
        __syncthreads();   // sB (and sA) visible

        // ---- GEMM: 4 K-tiles x 8 N-tiles, 3 mma each (hh, hl, lh) ----
#pragma unroll
        for (int kt = 0; kt < 4; kt++) {
            const int ko = kt * 8;
            uint32_t ah0 = pAh[ko],       ah1 = pAh[ko + 288];
            uint32_t ah2 = pAh[ko + 4],   ah3 = pAh[ko + 292];
            uint32_t al0 = pAl[ko],       al1 = pAl[ko + 288];
            uint32_t al2 = pAl[ko + 4],   al3 = pAl[ko + 292];
#pragma unroll
            for (int nt = 0; nt < 8; nt++) {
                uint32_t bh0 = pB[nt * 288 + ko],        bh1 = pB[nt * 288 + ko + 4];
                uint32_t bl0 = pB[nt * 288 + ko + 2304], bl1 = pB[nt * 288 + ko + 2308];
                mma_bf16(acc[nt], ah0, ah1, ah2, ah3, bh0, bh1);
                mma_bf16(acc[nt], ah0, ah1, ah2, ah3, bl0, bl1);
                mma_bf16(acc[nt], al0, al1, al2, al3, bh0, bh1);
            }
        }
    }

    // ---- epilogue: d0=(g,2tg) d1=(g,2tg+1) d2=(g+8,2tg) d3=(g+8,2tg+1) ----
    const int px0 = pxw + g;
#pragma unroll
    for (int nt = 0; nt < 8; nt++) {
        const int o = nt * 8 + 2 * tg;
        const float b0 = __ldg(&bias[o]);
        const float b1 = __ldg(&bias[o + 1]);
        float* r0 = out + (((size_t)b * C_ + o)     * H_ + y) * W_;
        float* r1 = out + (((size_t)b * C_ + o + 1) * H_ + y) * W_;
        r0[px0]     = acc[nt].x + b0;
        r1[px0]     = acc[nt].y + b1;
        r0[px0 + 8] = acc[nt].z + b0;
        r1[px0 + 8] = acc[nt].w + b1;
    }
}

// ---------------- launch ----------------
extern "C" void kernel_launch(void* const* d_in, const int* in_sizes, int n_in,
                              void* d_out, int out_size) {
    const float* x           = (const float*)d_in[0];
    const float* offset_feat = (const float*)d_in[1];
    const float* w_off       = (const float*)d_in[2];
    const float* b_off       = (const float*)d_in[3];
    const float* weight      = (const float*)d_in[4];
    const float* bias        = (const float*)d_in[5];
    float* out = (float*)d_out;

    static bool attr_set = false;
    if (!attr_set) {
        cudaFuncSetAttribute(deform_kernel,
                             cudaFuncAttributeMaxDynamicSharedMemorySize,
                             SMU_TOT * 4);
        attr_set = true;
    }

    prep_w_kernel<<<(C_ * 32 * K2_ + 255) / 256, 256>>>(weight);
    nhwc_kernel<<<B_ * H_, 256>>>(x);
    offset_kernel<<<B_ * H_, 128>>>(offset_feat, w_off, b_off);
    deform_kernel<<<B_ * H_, 256, SMU_TOT * 4>>>(bias, out);
}

// round 7
// speedup vs baseline: 2.4070x; 1.1049x over previous
#include <cuda_runtime.h>
#include <math.h>
#include <cstdint>

typedef unsigned long long ull;

// Problem constants
#define B_    4
#define C_    64
#define H_    128
#define W_    128
#define HW_   (H_*W_)
#define OFFC_ 32
#define K2_   9
#define OCOFF 27

// ---------------- scratch ----------------
__device__ int    g_idx[B_ * K2_ * HW_];   // packed clamped corners
__device__ float4 g_wts[B_ * K2_ * HW_];   // premultiplied bilinear weights
__device__ float  g_xt[B_ * HW_ * C_];     // x in NHWC: [b][y][x][c]
// W^T as bf16x2 pairs, split hi/lo: [k][s][o][36 stride, 32 pairs used]
__device__ uint32_t g_wb[K2_ * 2 * C_ * 36];

// ---------------- helpers ----------------
__device__ __forceinline__ uint32_t smem_u32(const void* p) {
    uint32_t a;
    asm("{ .reg .u64 t; cvta.to.shared.u64 t, %1; cvt.u32.u64 %0, t; }" : "=r"(a) : "l"(p));
    return a;
}
__device__ __forceinline__ uint32_t bf16x2_pack(float hi_up, float lo_lo) {
    uint32_t d;
    asm("cvt.rn.bf16x2.f32 %0, %1, %2;" : "=r"(d) : "f"(hi_up), "f"(lo_lo));
    return d;
}
__device__ __forceinline__ void ffma2(ull& d, ull a, ull b) {
    asm("fma.rn.f32x2 %0, %1, %2, %0;" : "+l"(d) : "l"(a), "l"(b));
}
__device__ __forceinline__ ull dup2(float s) {
    ull d;
    asm("mov.b64 %0, {%1, %1};" : "=l"(d) : "f"(s));
    return d;
}
__device__ __forceinline__ void mma_bf16(float4& d,
                                         uint32_t a0, uint32_t a1, uint32_t a2, uint32_t a3,
                                         uint32_t b0, uint32_t b1) {
    asm volatile(
        "mma.sync.aligned.m16n8k16.row.col.f32.bf16.bf16.f32 "
        "{%0,%1,%2,%3}, {%4,%5,%6,%7}, {%8,%9}, {%0,%1,%2,%3};"
        : "+f"(d.x), "+f"(d.y), "+f"(d.z), "+f"(d.w)
        : "r"(a0), "r"(a1), "r"(a2), "r"(a3), "r"(b0), "r"(b1));
}
#define LDSM4(r0, r1, r2, r3, addr)                                           \
    asm volatile("ldmatrix.sync.aligned.m8n8.x4.shared.b16 {%0,%1,%2,%3}, [%4];" \
                 : "=r"(r0), "=r"(r1), "=r"(r2), "=r"(r3) : "r"(addr))

// ---------------- Stage 0a: weight -> bf16 hi/lo pairs, [k][s][o][pair] ----------------
__global__ void prep_w_kernel(const float* __restrict__ w) {
    int i = blockIdx.x * 256 + threadIdx.x;    // over 64o * 32p * 9k
    if (i >= C_ * 32 * K2_) return;
    int k = i % K2_;
    int t = i / K2_;
    int p = t % 32;
    int o = t / 32;
    float v0 = w[((size_t)o * C_ + 2 * p)     * K2_ + k];
    float v1 = w[((size_t)o * C_ + 2 * p + 1) * K2_ + k];
    uint32_t h = bf16x2_pack(v1, v0);
    float r0 = __uint_as_float(h << 16);
    float r1 = __uint_as_float(h & 0xffff0000u);
    uint32_t l = bf16x2_pack(v1 - r1, v0 - r0);
    g_wb[((size_t)(k * 2 + 0) * C_ + o) * 36 + p] = h;
    g_wb[((size_t)(k * 2 + 1) * C_ + o) * 36 + p] = l;
}

// ---------------- Stage 0b: x NCHW -> NHWC ----------------
__global__ __launch_bounds__(256) void nhwc_kernel(const float* __restrict__ x) {
    __shared__ float st[C_ * 129];
    const int tid = threadIdx.x;
    const int y   = blockIdx.x & (H_ - 1);
    const int b   = blockIdx.x >> 7;

    const float* src = x + ((size_t)b * C_ * H_ + y) * W_;
#pragma unroll
    for (int i = 0; i < 8; i++) {
        int idx = tid + i * 256;
        int c   = idx >> 5;
        int x4  = idx & 31;
        float4 v = __ldg((const float4*)(src + (size_t)c * HW_) + x4);
        float* d = st + c * 129 + x4 * 4;
        d[0] = v.x; d[1] = v.y; d[2] = v.z; d[3] = v.w;
    }
    __syncthreads();

    float* dst = g_xt + ((size_t)(b * H_ + y) * W_) * C_;
#pragma unroll
    for (int i = 0; i < 8; i++) {
        int idx = tid + i * 256;
        int px  = idx >> 4;
        int cq  = idx & 15;
        float4 v;
        v.x = st[(cq * 4 + 0) * 129 + px];
        v.y = st[(cq * 4 + 1) * 129 + px];
        v.z = st[(cq * 4 + 2) * 129 + px];
        v.w = st[(cq * 4 + 3) * 129 + px];
        *((float4*)(dst + (size_t)px * C_) + cq) = v;
    }
}

// ---------------- Stage 1: offset conv + bilinear descriptor precompute ----------------
__global__ __launch_bounds__(128) void offset_kernel(
    const float* __restrict__ offset_feat,   // [B,32,H,W]
    const float* __restrict__ w_off,         // [27,32,3,3]
    const float* __restrict__ b_off)         // [27]
{
    __shared__ __align__(16) float s_w[288 * 28];
    __shared__ __align__(16) float s_boff[28];

    const int tid = threadIdx.x;
    const int y   = blockIdx.x & (H_ - 1);
    const int b   = blockIdx.x >> 7;
    const int x   = tid;

    for (int i = tid; i < OCOFF * 288; i += 128) {
        int oc = i / 288;
        int r  = i % 288;
        s_w[r * 28 + oc] = w_off[i];
    }
    if (tid < 28) s_boff[tid] = (tid < OCOFF) ? b_off[tid] : 0.f;
    __syncthreads();

    ull acc2[14];
#pragma unroll
    for (int j = 0; j < 14; j++) acc2[j] = ((const ull*)s_boff)[j];

    const float* fbase = offset_feat + (size_t)b * OFFC_ * HW_;

#pragma unroll
    for (int ky = 0; ky < 3; ky++) {
        const int iy = y - 1 + ky;
        const bool vy = ((unsigned)iy < (unsigned)H_);
#pragma unroll
        for (int kx = 0; kx < 3; kx++) {
            const int ix = x - 1 + kx;
            const bool v = vy && ((unsigned)ix < (unsigned)W_);
            const int tap = ky * 3 + kx;
            const float* ip = fbase + iy * W_ + ix;
#pragma unroll 4
            for (int c = 0; c < OFFC_; c++) {
                float vv = v ? __ldg(ip + c * HW_) : 0.f;
                ull v2 = dup2(vv);
                const ulonglong2* wp = (const ulonglong2*)(s_w + (c * 9 + tap) * 28);
#pragma unroll
                for (int j = 0; j < 7; j++) {
                    ulonglong2 ww = wp[j];
                    ffma2(acc2[2 * j],     ww.x, v2);
                    ffma2(acc2[2 * j + 1], ww.y, v2);
                }
            }
        }
    }

    float acc[28];
#pragma unroll
    for (int j = 0; j < 14; j++) {
        asm("mov.b64 {%0, %1}, %2;" : "=f"(acc[2 * j]), "=f"(acc[2 * j + 1]) : "l"(acc2[j]));
    }

#pragma unroll
    for (int k = 0; k < K2_; k++) {
        float dy = acc[2 * k];
        float dx = acc[2 * k + 1];
        float m  = 1.f / (1.f + __expf(-acc[18 + k]));

        float py = (float)(y - 1 + (k / 3)) + dy;
        float px = (float)(x - 1 + (k % 3)) + dx;
        float y0f = floorf(py), x0f = floorf(px);
        float wy1 = py - y0f,   wx1 = px - x0f;
        float wy0 = 1.f - wy1,  wx0 = 1.f - wx1;
        int y0 = (int)y0f, x0 = (int)x0f;
        int y1 = y0 + 1,   x1 = x0 + 1;

        bool vy0 = ((unsigned)y0 < (unsigned)H_);
        bool vy1 = ((unsigned)y1 < (unsigned)H_);
        bool vx0 = ((unsigned)x0 < (unsigned)W_);
        bool vx1 = ((unsigned)x1 < (unsigned)W_);

        float w00 = wy0 * wx0 * m * (float)(vy0 && vx0);
        float w01 = wy0 * wx1 * m * (float)(vy0 && vx1);
        float w10 = wy1 * wx0 * m * (float)(vy1 && vx0);
        float w11 = wy1 * wx1 * m * (float)(vy1 && vx1);

        int y0c = min(max(y0, 0), H_ - 1);
        int y1c = min(max(y1, 0), H_ - 1);
        int x0c = min(max(x0, 0), W_ - 1);
        int x1c = min(max(x1, 0), W_ - 1);

        int base = ((b * K2_ + k) * H_ + y) * W_ + x;
        g_idx[base] = (y0c << 24) | (y1c << 16) | (x0c << 8) | x1c;
        g_wts[base] = make_float4(w00, w01, w10, w11);
    }
}

// ---------------- Stage 2: NHWC gather fill + mma.sync bf16 + ldmatrix ----------------
// block = one (b,y) row, 8 warps; warp w owns px strip [16w,16w+16).
// Per tap: fill(k) [warp-private, overlaps neighbors' GEMM(k-1)] -> barrier ->
// copy B(k+1) into alternate buffer -> syncwarp -> GEMM(k) via ldmatrix.x4.
// smem u32: sAh[128][36] sAl[128][36] sBbuf0[4608] sBbuf1[4608] = 73728 B
#define SMU_AH  0
#define SMU_AL  4608
#define SMU_B0  9216
#define SMU_B1  13824
#define SMU_TOT 18432

__global__ __launch_bounds__(256) void deform_kernel(
    const float* __restrict__ bias,  // [64]
    float* __restrict__ out)         // [B,64,H,W]
{
    extern __shared__ uint32_t usm[];
    uint32_t* sAh = usm + SMU_AH;
    uint32_t* sAl = usm + SMU_AL;

    const int tid = threadIdx.x;
    const int wid = tid >> 5;
    const int lid = tid & 31;
    const int y   = blockIdx.x & (H_ - 1);
    const int b   = blockIdx.x >> 7;

    const int pxw = wid * 16;
    const int g   = lid >> 2;
    const int tg  = lid & 3;
    const int c4  = lid & 15;

    const uint32_t smb = smem_u32(usm);
    // ldmatrix lane roles: tile t8 = lid>>3, row r8 = lid&7
    const int t8 = lid >> 3, r8 = lid & 7;
    // A: tiles (rows0-7,k0-7),(rows8-15,k0-7),(rows0-7,k8-15),(rows8-15,k8-15)
    const uint32_t aOffH = smb + 4u * ((uint32_t)(pxw + (t8 & 1) * 8 + r8) * 36u
                                       + (uint32_t)(t8 >> 1) * 4u);
    const uint32_t aOffL = aOffH + 4u * 4608u;
    // B: tiles (hi b0),(hi b1),(lo b0),(lo b1); hi at +0, lo at +2304 u32
    const uint32_t bRow = 4u * ((uint32_t)(t8 >> 1) * 2304u + (uint32_t)r8 * 36u
                                + (uint32_t)(t8 & 1) * 4u);
    const uint32_t bBase0 = smb + 4u * SMU_B0;
    const uint32_t bBase1 = smb + 4u * SMU_B1;

    float4 acc[8];
#pragma unroll
    for (int nt = 0; nt < 8; nt++) acc[nt] = make_float4(0.f, 0.f, 0.f, 0.f);

    const float* xtb = g_xt + (size_t)b * HW_ * C_;

    // ---- prologue: copy B(0) into buf0 ----
    {
        const float4* src = (const float4*)g_wb;
        float4* dst = (float4*)(usm + SMU_B0);
#pragma unroll
        for (int i = 0; i < 4; i++)
            dst[tid + i * 256] = __ldg(src + tid + i * 256);
        int i4 = tid + 1024;
        if (i4 < 1152) dst[i4] = __ldg(src + i4);
    }

#pragma unroll 1
    for (int k = 0; k < K2_; k++) {
        // ---- warp-private bilinear fill of sA rows [pxw, pxw+16) ----
        {
            const int dbase = ((b * K2_ + k) * H_ + y) * W_;
#pragma unroll
            for (int j = 0; j < 8; j++) {
                const int px = pxw + 2 * j + (lid >> 4);
                const float4 wv = __ldg(&g_wts[dbase + px]);
                const int    di = __ldg(&g_idx[dbase + px]);
                const int y0c = (di >> 24) & 255, y1c = (di >> 16) & 255;
                const int x0c = (di >> 8) & 255,  x1c = di & 255;
                const float4 q00 = __ldg((const float4*)(xtb + (size_t)(y0c * W_ + x0c) * C_) + c4);
                const float4 q01 = __ldg((const float4*)(xtb + (size_t)(y0c * W_ + x1c) * C_) + c4);
                const float4 q10 = __ldg((const float4*)(xtb + (size_t)(y1c * W_ + x0c) * C_) + c4);
                const float4 q11 = __ldg((const float4*)(xtb + (size_t)(y1c * W_ + x1c) * C_) + c4);
                float v0 = wv.x * q00.x + wv.y * q01.x + wv.z * q10.x + wv.w * q11.x;
                float v1 = wv.x * q00.y + wv.y * q01.y + wv.z * q10.y + wv.w * q11.y;
                float v2 = wv.x * q00.z + wv.y * q01.z + wv.z * q10.z + wv.w * q11.z;
                float v3 = wv.x * q00.w + wv.y * q01.w + wv.z * q10.w + wv.w * q11.w;
                uint32_t h0 = bf16x2_pack(v1, v0);
                uint32_t h1 = bf16x2_pack(v3, v2);
                float r0 = __uint_as_float(h0 << 16);
                float r1 = __uint_as_float(h0 & 0xffff0000u);
                float r2 = __uint_as_float(h1 << 16);
                float r3 = __uint_as_float(h1 & 0xffff0000u);
                uint32_t l0 = bf16x2_pack(v1 - r1, v0 - r0);
                uint32_t l1 = bf16x2_pack(v3 - r3, v2 - r2);
                *(uint2*)&sAh[px * 36 + 2 * c4] = make_uint2(h0, h1);
                *(uint2*)&sAl[px * 36 + 2 * c4] = make_uint2(l0, l1);
            }
        }

        // barrier: (a) B(k) copy complete, (b) all GEMM(k-1) done before we
        // overwrite buf[(k+1)&1] below
        __syncthreads();

        // ---- cooperative copy of B(k+1) into alternate buffer ----
        if (k + 1 < K2_) {
            const float4* src = (const float4*)(g_wb + (size_t)(k + 1) * 4608);
            float4* dst = (float4*)(usm + (((k + 1) & 1) ? SMU_B1 : SMU_B0));
#pragma unroll
            for (int i = 0; i < 4; i++)
                dst[tid + i * 256] = __ldg(src + tid + i * 256);
            int i4 = tid + 1024;
            if (i4 < 1152) dst[i4] = __ldg(src + i4);
        }

        __syncwarp();   // sA fill (cross-lane) visible to ldmatrix

        // ---- GEMM: ldmatrix + 96 mma (hh, hl, lh) ----
        const uint32_t bB = (k & 1) ? bBase1 : bBase0;
#pragma unroll
        for (int kt = 0; kt < 4; kt++) {
            uint32_t ah0, ah1, ah2, ah3, al0, al1, al2, al3;
            LDSM4(ah0, ah1, ah2, ah3, aOffH + kt * 32u);
            LDSM4(al0, al1, al2, al3, aOffL + kt * 32u);
#pragma unroll
            for (int nt = 0; nt < 8; nt++) {
                uint32_t bh0, bh1, bl0, bl1;
                LDSM4(bh0, bh1, bl0, bl1, bB + bRow + (uint32_t)nt * 1152u + kt * 32u);
                mma_bf16(acc[nt], ah0, ah1, ah2, ah3, bh0, bh1);
                mma_bf16(acc[nt], ah0, ah1, ah2, ah3, bl0, bl1);
                mma_bf16(acc[nt], al0, al1, al2, al3, bh0, bh1);
            }
        }
    }

    // ---- epilogue ----
    const int px0 = pxw + g;
#pragma unroll
    for (int nt = 0; nt < 8; nt++) {
        const int o = nt * 8 + 2 * tg;
        const float b0 = __ldg(&bias[o]);
        const float b1 = __ldg(&bias[o + 1]);
        float* r0 = out + (((size_t)b * C_ + o)     * H_ + y) * W_;
        float* r1 = out + (((size_t)b * C_ + o + 1) * H_ + y) * W_;
        r0[px0]     = acc[nt].x + b0;
        r1[px0]     = acc[nt].y + b1;
        r0[px0 + 8] = acc[nt].z + b0;
        r1[px0 + 8] = acc[nt].w + b1;
    }
}

// ---------------- launch ----------------
extern "C" void kernel_launch(void* const* d_in, const int* in_sizes, int n_in,
                              void* d_out, int out_size) {
    const float* x           = (const float*)d_in[0];
    const float* offset_feat = (const float*)d_in[1];
    const float* w_off       = (const float*)d_in[2];
    const float* b_off       = (const float*)d_in[3];
    const float* weight      = (const float*)d_in[4];
    const float* bias        = (const float*)d_in[5];
    float* out = (float*)d_out;

    static bool attr_set = false;
    if (!attr_set) {
        cudaFuncSetAttribute(deform_kernel,
                             cudaFuncAttributeMaxDynamicSharedMemorySize,
                             SMU_TOT * 4);
        attr_set = true;
    }

    prep_w_kernel<<<(C_ * 32 * K2_ + 255) / 256, 256>>>(weight);
    nhwc_kernel<<<B_ * H_, 256>>>(x);
    offset_kernel<<<B_ * H_, 128>>>(offset_feat, w_off, b_off);
    deform_kernel<<<B_ * H_, 256, SMU_TOT * 4>>>(bias, out);
}